// round 3
// baseline (speedup 1.0000x reference)
#include <cuda_runtime.h>

// MHA fwd B=4 H=16 S=2048 Dk=4; outputs out [B,H,S,4] then attn [B,H,S,S] in d_out.
//
// R2/R3: warp-per-key-slice layout. Block = (b, 16-query tile), 16 warps; warp w owns
// keys [w*128, w*128+128), lane owns 4 consecutive keys (one float4 granule = tid).
// Each thread loads its 4 K-vecs / 4 V-vecs from smem ONCE per head and loops all
// 16 queries (Q read via broadcast LDS) -> ~10x less smem crossbar than R1.
// Softmax without max-subtraction (scores bounded, masked lanes -> exact 0).
// Row sums and out = attn@V reduced via warp butterflies + smem partials.

#define SQ      2048
#define QT      16
#define NH      16
#define NB      4
#define THREADS 512
#define SQ4     512

// smem layout in floats
#define OFF_K    0            // 2048 float4 (swizzled: k -> (k&3)*512 + (k>>2))
#define OFF_V    8192
#define OFF_Q    16384        // 16 float4 (pre-scaled by 0.5)
#define OFF_WSUM 16448        // [16 q][17] per-warp partial row sums
#define OFF_RINV 16720        // [16] 1/rowsum
#define OFF_ORED 16736        // [16 w][68] per-warp partial out (q*4+c)
#define SMEM_FLOATS 17824

__global__ __launch_bounds__(THREADS, 1)
void mha_kernel(const float4* __restrict__ Q, const float4* __restrict__ K,
                const float4* __restrict__ V, const int*    __restrict__ mask,
                float* __restrict__ out, float4* __restrict__ attn)
{
    extern __shared__ float sm[];
    float4* Ks4  = (float4*)(sm + OFF_K);
    float4* Vs4  = (float4*)(sm + OFF_V);
    float4* Qt4  = (float4*)(sm + OFF_Q);
    float*  wsum = sm + OFF_WSUM;
    float*  rinv = sm + OFF_RINV;
    float*  ored = sm + OFF_ORED;

    const int tid  = threadIdx.x;           // == float4 granule index (4 keys)
    const int w    = tid >> 5;
    const int lane = tid & 31;
    const int qb   = blockIdx.x * QT;
    const int b    = blockIdx.y;

    // ---- pack mask[b][qb+q][my 4 keys] into 64 bits (bit q*4+j), reused all heads
    unsigned mb0 = 0u, mb1 = 0u;
    {
        const int4* m4 = (const int4*)mask + ((size_t)b * SQ + qb) * SQ4 + tid;
#pragma unroll
        for (int q = 0; q < QT; ++q) {
            int4 mv = m4[q * SQ4];
            unsigned bits = (mv.x != 0 ? 1u : 0u) | (mv.y != 0 ? 2u : 0u)
                          | (mv.z != 0 ? 4u : 0u) | (mv.w != 0 ? 8u : 0u);
            if (q < 8) mb0 |= bits << (q * 4);
            else       mb1 |= bits << ((q - 8) * 4);
        }
    }

    float sc[QT][4];   // exp(score) for my 4 keys x 16 queries

    for (int h = 0; h < NH; ++h) {
        const int bh = b * NH + h;

        __syncthreads();   // prev head: pass2 smem reads + ored writes done
        {
            const float4* Kb = K + (size_t)bh * SQ;
            const float4* Vb = V + (size_t)bh * SQ;
#pragma unroll
            for (int i = 0; i < 4; ++i) {
                int t  = tid + i * THREADS;
                int si = (t & 3) * SQ4 + (t >> 2);
                Ks4[si] = Kb[t];
                Vs4[si] = Vb[t];
            }
            if (tid < QT) {
                float4 qv = Q[(size_t)bh * SQ + qb + tid];
                qv.x *= 0.5f; qv.y *= 0.5f; qv.z *= 0.5f; qv.w *= 0.5f;
                Qt4[tid] = qv;
            }
            if (h > 0 && tid < 64) {    // finish previous head's out (overlaps staging)
                float s = 0.f;
#pragma unroll
                for (int ww = 0; ww < 16; ++ww) s += ored[ww * 68 + tid];
                out[((size_t)(bh - 1) * SQ + qb + (tid >> 2)) * 4 + (tid & 3)] = s;
            }
        }
        __syncthreads();

        // ---- pass 1: e = exp(q.k/2) (masked -> 0), per-row partial sums
        const float4 kv0 = Ks4[0 * SQ4 + tid];
        const float4 kv1 = Ks4[1 * SQ4 + tid];
        const float4 kv2 = Ks4[2 * SQ4 + tid];
        const float4 kv3 = Ks4[3 * SQ4 + tid];
#pragma unroll
        for (int q = 0; q < QT; ++q) {
            const float4 qv = Qt4[q];                       // smem broadcast
            const unsigned mb = ((q < 8) ? mb0 : mb1) >> ((q & 7) * 4);
            float s0 = qv.x*kv0.x + qv.y*kv0.y + qv.z*kv0.z + qv.w*kv0.w;
            float s1 = qv.x*kv1.x + qv.y*kv1.y + qv.z*kv1.z + qv.w*kv1.w;
            float s2 = qv.x*kv2.x + qv.y*kv2.y + qv.z*kv2.z + qv.w*kv2.w;
            float s3 = qv.x*kv3.x + qv.y*kv3.y + qv.z*kv3.z + qv.w*kv3.w;
            float e0 = (mb & 1u) ? __expf(s0) : 0.f;
            float e1 = (mb & 2u) ? __expf(s1) : 0.f;
            float e2 = (mb & 4u) ? __expf(s2) : 0.f;
            float e3 = (mb & 8u) ? __expf(s3) : 0.f;
            sc[q][0] = e0; sc[q][1] = e1; sc[q][2] = e2; sc[q][3] = e3;
            float ps = (e0 + e1) + (e2 + e3);
#pragma unroll
            for (int o = 16; o; o >>= 1) ps += __shfl_xor_sync(0xffffffffu, ps, o);
            if (lane == 0) wsum[q * 17 + w] = ps;
        }
        __syncthreads();
        if (tid < QT) {
            float s = 0.f;
#pragma unroll
            for (int ww = 0; ww < 16; ++ww) s += wsum[tid * 17 + ww];
            rinv[tid] = 1.0f / s;
        }
        __syncthreads();

        // ---- pass 2: normalize, write attn (STG.128), accumulate out partials
        const float4 vv0 = Vs4[0 * SQ4 + tid];
        const float4 vv1 = Vs4[1 * SQ4 + tid];
        const float4 vv2 = Vs4[2 * SQ4 + tid];
        const float4 vv3 = Vs4[3 * SQ4 + tid];
        float4* arow = attn + ((size_t)bh * SQ + qb) * SQ4 + tid;
#pragma unroll
        for (int q = 0; q < QT; ++q) {
            const float inv = rinv[q];                      // smem broadcast
            float p0 = sc[q][0] * inv, p1 = sc[q][1] * inv;
            float p2 = sc[q][2] * inv, p3 = sc[q][3] * inv;
            float4 pw; pw.x = p0; pw.y = p1; pw.z = p2; pw.w = p3;
            arow[(size_t)q * SQ4] = pw;
            float cx = p0*vv0.x + p1*vv1.x + p2*vv2.x + p3*vv3.x;
            float cy = p0*vv0.y + p1*vv1.y + p2*vv2.y + p3*vv3.y;
            float cz = p0*vv0.z + p1*vv1.z + p2*vv2.z + p3*vv3.z;
            float cw = p0*vv0.w + p1*vv1.w + p2*vv2.w + p3*vv3.w;
#pragma unroll
            for (int o = 16; o; o >>= 1) {
                cx += __shfl_xor_sync(0xffffffffu, cx, o);
                cy += __shfl_xor_sync(0xffffffffu, cy, o);
                cz += __shfl_xor_sync(0xffffffffu, cz, o);
                cw += __shfl_xor_sync(0xffffffffu, cw, o);
            }
            if (lane == 0) {
                float4 c4; c4.x = cx; c4.y = cy; c4.z = cz; c4.w = cw;
                *(float4*)(ored + w * 68 + q * 4) = c4;
            }
        }
    }

    // ---- final head's out reduction
    __syncthreads();
    if (tid < 64) {
        float s = 0.f;
#pragma unroll
        for (int ww = 0; ww < 16; ++ww) s += ored[ww * 68 + tid];
        out[((size_t)(b * NH + NH - 1) * SQ + qb + (tid >> 2)) * 4 + (tid & 3)] = s;
    }
}

extern "C" void kernel_launch(void* const* d_in, const int* in_sizes, int n_in,
                              void* d_out, int out_size)
{
    (void)in_sizes; (void)n_in; (void)out_size;
    const float4* Q    = (const float4*)d_in[0];
    const float4* K    = (const float4*)d_in[1];
    const float4* V    = (const float4*)d_in[2];
    const int*    mask = (const int*)   d_in[3];

    float* outp  = (float*)d_out;
    float* attnp = outp + (size_t)NB * NH * SQ * 4;   // attn follows out

    size_t smem = SMEM_FLOATS * sizeof(float);        // ~69.6 KB
    cudaFuncSetAttribute(mha_kernel, cudaFuncAttributeMaxDynamicSharedMemorySize, (int)smem);

    dim3 grid(SQ / QT, NB);
    mha_kernel<<<grid, THREADS, smem>>>(Q, K, V, mask, outp, (float4*)attnp);
}

// round 8
// speedup vs baseline: 1.2556x; 1.2556x over previous
#include <cuda_runtime.h>

// MHA fwd B=4 H=16 S=2048 Dk=4; outputs out [B,H,S,4] then attn [B,H,S,S] in d_out.
//
// R7/R8: occupancy fix. QT=8 (sc 32 regs), vv loaded in pass2 into registers freed
// by kv (dead after pass1), __launch_bounds__(512,2) -> <=64 regs -> 2 CTAs/SM (50%
// occ vs 25% in R1/R3, which were latency-bound, not pipe-bound). Butterflies halved
// (200/warp/head). exp via ex2.approx with log2e folded into the Q pre-scale.

#define SQ      2048
#define QT      8
#define NH      16
#define NB      4
#define THREADS 512
#define SQ4     512

// smem layout in floats
#define OFF_K    0            // 2048 float4, swizzled: granule t -> (t&3)*512 + (t>>2)
#define OFF_V    8192
#define OFF_Q    16384        // 8 float4, pre-scaled by 0.5*log2e
#define OFF_WSUM 16416        // [8 q][17]
#define OFF_RINV 16552        // [8]
#define OFF_ORED 16560        // [16 w][36] (q*4+c, padded)
#define SMEM_FLOATS 17136     // 68544 bytes

#define EX2F(d, s) asm("ex2.approx.f32 %0, %1;" : "=f"(d) : "f"(s))

__global__ __launch_bounds__(THREADS, 2)
void mha_kernel(const float4* __restrict__ Q, const float4* __restrict__ K,
                const float4* __restrict__ V, const int*    __restrict__ mask,
                float* __restrict__ out, float4* __restrict__ attn)
{
    extern __shared__ float sm[];
    float4* Ks4  = (float4*)(sm + OFF_K);
    float4* Vs4  = (float4*)(sm + OFF_V);
    float4* Qt4  = (float4*)(sm + OFF_Q);
    float*  wsum = sm + OFF_WSUM;
    float*  rinv = sm + OFF_RINV;
    float*  ored = sm + OFF_ORED;

    const int tid  = threadIdx.x;           // float4 granule: keys [4*tid, 4*tid+4)
    const int w    = tid >> 5;
    const int lane = tid & 31;
    const int qb   = blockIdx.x * QT;
    const int b    = blockIdx.y;

    // ---- pack mask[b][qb+q][my 4 keys] into one 32-bit word (bit q*4+j)
    unsigned mb = 0u;
    {
        const int4* m4 = (const int4*)mask + ((size_t)b * SQ + qb) * SQ4 + tid;
#pragma unroll
        for (int q = 0; q < QT; ++q) {
            int4 mv = m4[q * SQ4];
            unsigned bits = (mv.x != 0 ? 1u : 0u) | (mv.y != 0 ? 2u : 0u)
                          | (mv.z != 0 ? 4u : 0u) | (mv.w != 0 ? 8u : 0u);
            mb |= bits << (q * 4);
        }
    }

    float sc[QT][4];   // exp(score) for my 4 keys x 8 queries

    for (int h = 0; h < NH; ++h) {
        const int bh = b * NH + h;

        __syncthreads();   // prev head: pass2 smem reads + ored writes done
        {
            const float4* Kb = K + (size_t)bh * SQ;
            const float4* Vb = V + (size_t)bh * SQ;
#pragma unroll
            for (int i = 0; i < 4; ++i) {
                int t  = tid + i * THREADS;
                int si = (t & 3) * SQ4 + (t >> 2);
                Ks4[si] = Kb[t];
                Vs4[si] = Vb[t];
            }
            if (tid < QT) {
                float4 qv = Q[(size_t)bh * SQ + qb + tid];
                const float c = 0.72134752044448170f;   // 0.5 * log2(e)
                qv.x *= c; qv.y *= c; qv.z *= c; qv.w *= c;
                Qt4[tid] = qv;
            }
            if (h > 0 && tid < QT * 4) {   // finish previous head's out (overlaps staging)
                float s = 0.f;
#pragma unroll
                for (int ww = 0; ww < 16; ++ww) s += ored[ww * 36 + tid];
                out[((size_t)(bh - 1) * SQ + qb + (tid >> 2)) * 4 + (tid & 3)] = s;
            }
        }
        __syncthreads();

        // ---- pass 1: e = 2^(q.k*0.5*log2e) (masked -> 0), row partial sums
        {
            const float4 kv0 = Ks4[0 * SQ4 + tid];
            const float4 kv1 = Ks4[1 * SQ4 + tid];
            const float4 kv2 = Ks4[2 * SQ4 + tid];
            const float4 kv3 = Ks4[3 * SQ4 + tid];
#pragma unroll
            for (int q = 0; q < QT; ++q) {
                const float4 qv = Qt4[q];               // smem broadcast
                const unsigned mq = mb >> (q * 4);
                float s0 = qv.x*kv0.x + qv.y*kv0.y + qv.z*kv0.z + qv.w*kv0.w;
                float s1 = qv.x*kv1.x + qv.y*kv1.y + qv.z*kv1.z + qv.w*kv1.w;
                float s2 = qv.x*kv2.x + qv.y*kv2.y + qv.z*kv2.z + qv.w*kv2.w;
                float s3 = qv.x*kv3.x + qv.y*kv3.y + qv.z*kv3.z + qv.w*kv3.w;
                float e0, e1, e2, e3;
                EX2F(e0, s0); EX2F(e1, s1); EX2F(e2, s2); EX2F(e3, s3);
                e0 = (mq & 1u) ? e0 : 0.f;
                e1 = (mq & 2u) ? e1 : 0.f;
                e2 = (mq & 4u) ? e2 : 0.f;
                e3 = (mq & 8u) ? e3 : 0.f;
                sc[q][0] = e0; sc[q][1] = e1; sc[q][2] = e2; sc[q][3] = e3;
                float ps = (e0 + e1) + (e2 + e3);
#pragma unroll
                for (int o = 16; o; o >>= 1) ps += __shfl_xor_sync(0xffffffffu, ps, o);
                if (lane == 0) wsum[q * 17 + w] = ps;
            }
        }
        __syncthreads();
        if (tid < QT) {
            float s = 0.f;
#pragma unroll
            for (int ww = 0; ww < 16; ++ww) s += wsum[tid * 17 + ww];
            rinv[tid] = 1.0f / s;
        }
        __syncthreads();

        // ---- pass 2: normalize, write attn (STG.128), out partials (kv regs now dead)
        {
            const float4 vv0 = Vs4[0 * SQ4 + tid];
            const float4 vv1 = Vs4[1 * SQ4 + tid];
            const float4 vv2 = Vs4[2 * SQ4 + tid];
            const float4 vv3 = Vs4[3 * SQ4 + tid];
            float4* arow = attn + ((size_t)bh * SQ + qb) * SQ4 + tid;
#pragma unroll
            for (int q = 0; q < QT; ++q) {
                const float inv = rinv[q];              // smem broadcast
                float p0 = sc[q][0] * inv, p1 = sc[q][1] * inv;
                float p2 = sc[q][2] * inv, p3 = sc[q][3] * inv;
                float4 pw; pw.x = p0; pw.y = p1; pw.z = p2; pw.w = p3;
                arow[(size_t)q * SQ4] = pw;
                float cx = p0*vv0.x + p1*vv1.x + p2*vv2.x + p3*vv3.x;
                float cy = p0*vv0.y + p1*vv1.y + p2*vv2.y + p3*vv3.y;
                float cz = p0*vv0.z + p1*vv1.z + p2*vv2.z + p3*vv3.z;
                float cw = p0*vv0.w + p1*vv1.w + p2*vv2.w + p3*vv3.w;
#pragma unroll
                for (int o = 16; o; o >>= 1) {
                    cx += __shfl_xor_sync(0xffffffffu, cx, o);
                    cy += __shfl_xor_sync(0xffffffffu, cy, o);
                    cz += __shfl_xor_sync(0xffffffffu, cz, o);
                    cw += __shfl_xor_sync(0xffffffffu, cw, o);
                }
                if (lane == 0) {
                    float4 c4; c4.x = cx; c4.y = cy; c4.z = cz; c4.w = cw;
                    *(float4*)(ored + w * 36 + q * 4) = c4;
                }
            }
        }
    }

    // ---- final head's out reduction
    __syncthreads();
    if (tid < QT * 4) {
        float s = 0.f;
#pragma unroll
        for (int ww = 0; ww < 16; ++ww) s += ored[ww * 36 + tid];
        out[((size_t)(b * NH + NH - 1) * SQ + qb + (tid >> 2)) * 4 + (tid & 3)] = s;
    }
}

extern "C" void kernel_launch(void* const* d_in, const int* in_sizes, int n_in,
                              void* d_out, int out_size)
{
    (void)in_sizes; (void)n_in; (void)out_size;
    const float4* Q    = (const float4*)d_in[0];
    const float4* K    = (const float4*)d_in[1];
    const float4* V    = (const float4*)d_in[2];
    const int*    mask = (const int*)   d_in[3];

    float* outp  = (float*)d_out;
    float* attnp = outp + (size_t)NB * NH * SQ * 4;   // attn follows out

    size_t smem = SMEM_FLOATS * sizeof(float);        // 68544 B -> 2 CTAs/SM
    cudaFuncSetAttribute(mha_kernel, cudaFuncAttributeMaxDynamicSharedMemorySize, (int)smem);

    dim3 grid(SQ / QT, NB);
    mha_kernel<<<grid, THREADS, smem>>>(Q, K, V, mask, outp, (float4*)attnp);
}

// round 11
// speedup vs baseline: 1.6635x; 1.3248x over previous
#include <cuda_runtime.h>

// MHA fwd B=4 H=16 S=2048 Dk=4; outputs out [B,H,S,4] then attn [B,H,S,S] in d_out.
//
// R9/R10/R11: R8 (QT=8, 2 CTAs/SM, ex2.approx) + multi-value butterfly for the
// out=attn@V reduction. R8 was MIO-bound (L1=73.2%), dominated by 160 SHFL/warp/head
// in pass 2. Batches of 8 values (2 queries x 4 comps) reduce across 32 lanes in
// 9 SHFL (lane bits {16,8,4} route values, {2,1} accumulate); 36 SHFL/head vs 160,
// and predicated STS.32 replace the 8 STS.128.

#define SQ      2048
#define QT      8
#define NH      16
#define NB      4
#define THREADS 512
#define SQ4     512

// smem layout in floats
#define OFF_K    0            // 2048 float4, swizzled: granule t -> (t&3)*512 + (t>>2)
#define OFF_V    8192
#define OFF_Q    16384        // 8 float4, pre-scaled by 0.5*log2e
#define OFF_WSUM 16416        // [8 q][17]
#define OFF_RINV 16552        // [8]
#define OFF_ORED 16560        // [16 w][33] (q*4+c, padded)
#define SMEM_FLOATS 17088     // 68352 bytes

#define EX2F(d, s) asm("ex2.approx.f32 %0, %1;" : "=f"(d) : "f"(s))

__global__ __launch_bounds__(THREADS, 2)
void mha_kernel(const float4* __restrict__ Q, const float4* __restrict__ K,
                const float4* __restrict__ V, const int*    __restrict__ mask,
                float* __restrict__ out, float4* __restrict__ attn)
{
    extern __shared__ float sm[];
    float4* Ks4  = (float4*)(sm + OFF_K);
    float4* Vs4  = (float4*)(sm + OFF_V);
    float4* Qt4  = (float4*)(sm + OFF_Q);
    float*  wsum = sm + OFF_WSUM;
    float*  rinv = sm + OFF_RINV;
    float*  ored = sm + OFF_ORED;

    const int tid  = threadIdx.x;           // float4 granule: keys [4*tid, 4*tid+4)
    const int w    = tid >> 5;
    const int lane = tid & 31;
    const int qb   = blockIdx.x * QT;
    const int b    = blockIdx.y;

    // ---- pack mask[b][qb+q][my 4 keys] into one 32-bit word (bit q*4+j)
    unsigned mb = 0u;
    {
        const int4* m4 = (const int4*)mask + ((size_t)b * SQ + qb) * SQ4 + tid;
#pragma unroll
        for (int q = 0; q < QT; ++q) {
            int4 mv = m4[q * SQ4];
            unsigned bits = (mv.x != 0 ? 1u : 0u) | (mv.y != 0 ? 2u : 0u)
                          | (mv.z != 0 ? 4u : 0u) | (mv.w != 0 ? 8u : 0u);
            mb |= bits << (q * 4);
        }
    }

    float sc[QT][4];   // exp(score) for my 4 keys x 8 queries

    for (int h = 0; h < NH; ++h) {
        const int bh = b * NH + h;

        __syncthreads();   // prev head: pass2 smem reads + ored writes done
        {
            const float4* Kb = K + (size_t)bh * SQ;
            const float4* Vb = V + (size_t)bh * SQ;
#pragma unroll
            for (int i = 0; i < 4; ++i) {
                int t  = tid + i * THREADS;
                int si = (t & 3) * SQ4 + (t >> 2);
                Ks4[si] = Kb[t];
                Vs4[si] = Vb[t];
            }
            if (tid < QT) {
                float4 qv = Q[(size_t)bh * SQ + qb + tid];
                const float c = 0.72134752044448170f;   // 0.5 * log2(e)
                qv.x *= c; qv.y *= c; qv.z *= c; qv.w *= c;
                Qt4[tid] = qv;
            }
            if (h > 0 && tid < QT * 4) {   // finish previous head's out (overlaps staging)
                float s = 0.f;
#pragma unroll
                for (int ww = 0; ww < 16; ++ww) s += ored[ww * 33 + tid];
                out[((size_t)(bh - 1) * SQ + qb + (tid >> 2)) * 4 + (tid & 3)] = s;
            }
        }
        __syncthreads();

        // ---- pass 1: e = 2^(q.k*0.5*log2e) (masked -> 0), row partial sums
        {
            const float4 kv0 = Ks4[0 * SQ4 + tid];
            const float4 kv1 = Ks4[1 * SQ4 + tid];
            const float4 kv2 = Ks4[2 * SQ4 + tid];
            const float4 kv3 = Ks4[3 * SQ4 + tid];
#pragma unroll
            for (int q = 0; q < QT; ++q) {
                const float4 qv = Qt4[q];               // smem broadcast
                const unsigned mq = mb >> (q * 4);
                float s0 = qv.x*kv0.x + qv.y*kv0.y + qv.z*kv0.z + qv.w*kv0.w;
                float s1 = qv.x*kv1.x + qv.y*kv1.y + qv.z*kv1.z + qv.w*kv1.w;
                float s2 = qv.x*kv2.x + qv.y*kv2.y + qv.z*kv2.z + qv.w*kv2.w;
                float s3 = qv.x*kv3.x + qv.y*kv3.y + qv.z*kv3.z + qv.w*kv3.w;
                float e0, e1, e2, e3;
                EX2F(e0, s0); EX2F(e1, s1); EX2F(e2, s2); EX2F(e3, s3);
                e0 = (mq & 1u) ? e0 : 0.f;
                e1 = (mq & 2u) ? e1 : 0.f;
                e2 = (mq & 4u) ? e2 : 0.f;
                e3 = (mq & 8u) ? e3 : 0.f;
                sc[q][0] = e0; sc[q][1] = e1; sc[q][2] = e2; sc[q][3] = e3;
                float ps = (e0 + e1) + (e2 + e3);
#pragma unroll
                for (int o = 16; o; o >>= 1) ps += __shfl_xor_sync(0xffffffffu, ps, o);
                if (lane == 0) wsum[q * 17 + w] = ps;
            }
        }
        __syncthreads();
        if (tid < QT) {
            float s = 0.f;
#pragma unroll
            for (int ww = 0; ww < 16; ++ww) s += wsum[tid * 17 + ww];
            rinv[tid] = 1.0f / s;
        }
        __syncthreads();

        // ---- pass 2: normalize, write attn (STG.128), out partials via
        //      8-value multi-butterfly (9 SHFL per 2 queries)
        {
            const float4 vv0 = Vs4[0 * SQ4 + tid];
            const float4 vv1 = Vs4[1 * SQ4 + tid];
            const float4 vv2 = Vs4[2 * SQ4 + tid];
            const float4 vv3 = Vs4[3 * SQ4 + tid];
            float4* arow = attn + ((size_t)bh * SQ + qb) * SQ4 + tid;
            const bool h16 = (lane & 16) != 0;
            const bool h8  = (lane & 8)  != 0;
            const bool h4  = (lane & 4)  != 0;
#pragma unroll
            for (int batch = 0; batch < 4; ++batch) {
                float c[8];
#pragma unroll
                for (int qq = 0; qq < 2; ++qq) {
                    const int q = batch * 2 + qq;
                    const float inv = rinv[q];          // smem broadcast
                    float p0 = sc[q][0] * inv, p1 = sc[q][1] * inv;
                    float p2 = sc[q][2] * inv, p3 = sc[q][3] * inv;
                    float4 pw; pw.x = p0; pw.y = p1; pw.z = p2; pw.w = p3;
                    arow[(size_t)q * SQ4] = pw;
                    c[qq*4+0] = p0*vv0.x + p1*vv1.x + p2*vv2.x + p3*vv3.x;
                    c[qq*4+1] = p0*vv0.y + p1*vv1.y + p2*vv2.y + p3*vv3.y;
                    c[qq*4+2] = p0*vv0.z + p1*vv1.z + p2*vv2.z + p3*vv3.z;
                    c[qq*4+3] = p0*vv0.w + p1*vv1.w + p2*vv2.w + p3*vv3.w;
                }
                // round o=16: keep 4 of 8 (lane bit4 selects logical half)
#pragma unroll
                for (int i = 0; i < 4; ++i) {
                    float send = h16 ? c[i] : c[i + 4];
                    float recv = __shfl_xor_sync(0xffffffffu, send, 16);
                    c[i] = (h16 ? c[i + 4] : c[i]) + recv;
                }
                // round o=8: keep 2 of 4
#pragma unroll
                for (int i = 0; i < 2; ++i) {
                    float send = h8 ? c[i] : c[i + 2];
                    float recv = __shfl_xor_sync(0xffffffffu, send, 8);
                    c[i] = (h8 ? c[i + 2] : c[i]) + recv;
                }
                // round o=4: keep 1 of 2
                {
                    float send = h4 ? c[0] : c[1];
                    float recv = __shfl_xor_sync(0xffffffffu, send, 4);
                    c[0] = (h4 ? c[1] : c[0]) + recv;
                }
                // finish over lane bits {2,1}
                c[0] += __shfl_xor_sync(0xffffffffu, c[0], 2);
                c[0] += __shfl_xor_sync(0xffffffffu, c[0], 1);
                // lane l holds value (l>>2)&7 of this batch, fully reduced
                if ((lane & 3) == 0)
                    ored[w * 33 + batch * 8 + ((lane >> 2) & 7)] = c[0];
            }
        }
    }

    // ---- final head's out reduction
    __syncthreads();
    if (tid < QT * 4) {
        float s = 0.f;
#pragma unroll
        for (int ww = 0; ww < 16; ++ww) s += ored[ww * 33 + tid];
        out[((size_t)(b * NH + NH - 1) * SQ + qb + (tid >> 2)) * 4 + (tid & 3)] = s;
    }
}

extern "C" void kernel_launch(void* const* d_in, const int* in_sizes, int n_in,
                              void* d_out, int out_size)
{
    (void)in_sizes; (void)n_in; (void)out_size;
    const float4* Q    = (const float4*)d_in[0];
    const float4* K    = (const float4*)d_in[1];
    const float4* V    = (const float4*)d_in[2];
    const int*    mask = (const int*)   d_in[3];

    float* outp  = (float*)d_out;
    float* attnp = outp + (size_t)NB * NH * SQ * 4;   // attn follows out

    size_t smem = SMEM_FLOATS * sizeof(float);        // 68352 B -> 2 CTAs/SM
    cudaFuncSetAttribute(mha_kernel, cudaFuncAttributeMaxDynamicSharedMemorySize, (int)smem);

    dim3 grid(SQ / QT, NB);
    mha_kernel<<<grid, THREADS, smem>>>(Q, K, V, mask, outp, (float4*)attnp);
}

// round 12
// speedup vs baseline: 1.7394x; 1.0457x over previous
#include <cuda_runtime.h>

// MHA fwd B=4 H=16 S=2048 Dk=4; outputs out [B,H,S,4] then attn [B,H,S,S] in d_out.
//
// R12: R11 + batched pass-1 row-sum reduction. R11 measured L1=69.4% (MIO-bound);
// pass 1 still burned 40 SHFL + 8 STS per warp/head on per-query butterflies.
// Two 4-value batched butterflies (lane bits {16,8} route, {4,2,1} finish) do it
// in 12 SHFL + 2 predicated STS. rinv read as 4x LDS.64 instead of 8x LDS.32.
// MIO instr/warp/head ~120 -> ~89.

#define SQ      2048
#define QT      8
#define NH      16
#define NB      4
#define THREADS 512
#define SQ4     512

// smem layout in floats
#define OFF_K    0            // 2048 float4, swizzled: granule t -> (t&3)*512 + (t>>2)
#define OFF_V    8192
#define OFF_Q    16384        // 8 float4, pre-scaled by 0.5*log2e
#define OFF_WSUM 16416        // [8 q][17]
#define OFF_RINV 16552        // [8]
#define OFF_ORED 16560        // [16 w][33] (q*4+c, padded)
#define SMEM_FLOATS 17088     // 68352 bytes

#define EX2F(d, s) asm("ex2.approx.f32 %0, %1;" : "=f"(d) : "f"(s))

__global__ __launch_bounds__(THREADS, 2)
void mha_kernel(const float4* __restrict__ Q, const float4* __restrict__ K,
                const float4* __restrict__ V, const int*    __restrict__ mask,
                float* __restrict__ out, float4* __restrict__ attn)
{
    extern __shared__ float sm[];
    float4* Ks4  = (float4*)(sm + OFF_K);
    float4* Vs4  = (float4*)(sm + OFF_V);
    float4* Qt4  = (float4*)(sm + OFF_Q);
    float*  wsum = sm + OFF_WSUM;
    float*  rinv = sm + OFF_RINV;
    float*  ored = sm + OFF_ORED;

    const int tid  = threadIdx.x;           // float4 granule: keys [4*tid, 4*tid+4)
    const int w    = tid >> 5;
    const int lane = tid & 31;
    const int qb   = blockIdx.x * QT;
    const int b    = blockIdx.y;

    const bool h16 = (lane & 16) != 0;
    const bool h8  = (lane & 8)  != 0;
    const bool h4  = (lane & 4)  != 0;

    // ---- pack mask[b][qb+q][my 4 keys] into one 32-bit word (bit q*4+j)
    unsigned mb = 0u;
    {
        const int4* m4 = (const int4*)mask + ((size_t)b * SQ + qb) * SQ4 + tid;
#pragma unroll
        for (int q = 0; q < QT; ++q) {
            int4 mv = m4[q * SQ4];
            unsigned bits = (mv.x != 0 ? 1u : 0u) | (mv.y != 0 ? 2u : 0u)
                          | (mv.z != 0 ? 4u : 0u) | (mv.w != 0 ? 8u : 0u);
            mb |= bits << (q * 4);
        }
    }

    float sc[QT][4];   // exp(score) for my 4 keys x 8 queries

    for (int h = 0; h < NH; ++h) {
        const int bh = b * NH + h;

        __syncthreads();   // prev head: pass2 smem reads + ored writes done
        {
            const float4* Kb = K + (size_t)bh * SQ;
            const float4* Vb = V + (size_t)bh * SQ;
#pragma unroll
            for (int i = 0; i < 4; ++i) {
                int t  = tid + i * THREADS;
                int si = (t & 3) * SQ4 + (t >> 2);
                Ks4[si] = Kb[t];
                Vs4[si] = Vb[t];
            }
            if (tid < QT) {
                float4 qv = Q[(size_t)bh * SQ + qb + tid];
                const float c = 0.72134752044448170f;   // 0.5 * log2(e)
                qv.x *= c; qv.y *= c; qv.z *= c; qv.w *= c;
                Qt4[tid] = qv;
            }
            if (h > 0 && tid < QT * 4) {   // finish previous head's out (overlaps staging)
                float s = 0.f;
#pragma unroll
                for (int ww = 0; ww < 16; ++ww) s += ored[ww * 33 + tid];
                out[((size_t)(bh - 1) * SQ + qb + (tid >> 2)) * 4 + (tid & 3)] = s;
            }
        }
        __syncthreads();

        // ---- pass 1: e = 2^(q.k*0.5*log2e) (masked -> 0); row sums via two
        //      4-value batched butterflies (6 SHFL per 4 queries)
        {
            const float4 kv0 = Ks4[0 * SQ4 + tid];
            const float4 kv1 = Ks4[1 * SQ4 + tid];
            const float4 kv2 = Ks4[2 * SQ4 + tid];
            const float4 kv3 = Ks4[3 * SQ4 + tid];
#pragma unroll
            for (int half = 0; half < 2; ++half) {
                float ps[4];
#pragma unroll
                for (int qq = 0; qq < 4; ++qq) {
                    const int q = half * 4 + qq;
                    const float4 qv = Qt4[q];           // smem broadcast
                    const unsigned mq = mb >> (q * 4);
                    float s0 = qv.x*kv0.x + qv.y*kv0.y + qv.z*kv0.z + qv.w*kv0.w;
                    float s1 = qv.x*kv1.x + qv.y*kv1.y + qv.z*kv1.z + qv.w*kv1.w;
                    float s2 = qv.x*kv2.x + qv.y*kv2.y + qv.z*kv2.z + qv.w*kv2.w;
                    float s3 = qv.x*kv3.x + qv.y*kv3.y + qv.z*kv3.z + qv.w*kv3.w;
                    float e0, e1, e2, e3;
                    EX2F(e0, s0); EX2F(e1, s1); EX2F(e2, s2); EX2F(e3, s3);
                    e0 = (mq & 1u) ? e0 : 0.f;
                    e1 = (mq & 2u) ? e1 : 0.f;
                    e2 = (mq & 4u) ? e2 : 0.f;
                    e3 = (mq & 8u) ? e3 : 0.f;
                    sc[q][0] = e0; sc[q][1] = e1; sc[q][2] = e2; sc[q][3] = e3;
                    ps[qq] = (e0 + e1) + (e2 + e3);
                }
                // 4-value butterfly: bits {16,8} route, {4,2,1} finish
                float s0 = h16 ? ps[0] : ps[2];
                float r0 = __shfl_xor_sync(0xffffffffu, s0, 16);
                float s1 = h16 ? ps[1] : ps[3];
                float r1 = __shfl_xor_sync(0xffffffffu, s1, 16);
                float a0 = (h16 ? ps[2] : ps[0]) + r0;
                float a1 = (h16 ? ps[3] : ps[1]) + r1;
                float s2 = h8 ? a0 : a1;
                float r2 = __shfl_xor_sync(0xffffffffu, s2, 8);
                a0 = (h8 ? a1 : a0) + r2;
                a0 += __shfl_xor_sync(0xffffffffu, a0, 4);
                a0 += __shfl_xor_sync(0xffffffffu, a0, 2);
                a0 += __shfl_xor_sync(0xffffffffu, a0, 1);
                // lane l holds query half*4 + ((l>>3)&3), fully reduced
                if ((lane & 7) == 0)
                    wsum[(half * 4 + ((lane >> 3) & 3)) * 17 + w] = a0;
            }
        }
        __syncthreads();
        if (tid < QT) {
            float s = 0.f;
#pragma unroll
            for (int ww = 0; ww < 16; ++ww) s += wsum[tid * 17 + ww];
            rinv[tid] = 1.0f / s;
        }
        __syncthreads();

        // ---- pass 2: normalize, write attn (STG.128), out partials via
        //      8-value multi-butterfly (9 SHFL per 2 queries)
        {
            const float4 vv0 = Vs4[0 * SQ4 + tid];
            const float4 vv1 = Vs4[1 * SQ4 + tid];
            const float4 vv2 = Vs4[2 * SQ4 + tid];
            const float4 vv3 = Vs4[3 * SQ4 + tid];
            float4* arow = attn + ((size_t)bh * SQ + qb) * SQ4 + tid;
#pragma unroll
            for (int batch = 0; batch < 4; ++batch) {
                const float2 rq = *(const float2*)(rinv + batch * 2);   // LDS.64 broadcast
                float c[8];
#pragma unroll
                for (int qq = 0; qq < 2; ++qq) {
                    const int q = batch * 2 + qq;
                    const float inv = qq ? rq.y : rq.x;
                    float p0 = sc[q][0] * inv, p1 = sc[q][1] * inv;
                    float p2 = sc[q][2] * inv, p3 = sc[q][3] * inv;
                    float4 pw; pw.x = p0; pw.y = p1; pw.z = p2; pw.w = p3;
                    arow[(size_t)q * SQ4] = pw;
                    c[qq*4+0] = p0*vv0.x + p1*vv1.x + p2*vv2.x + p3*vv3.x;
                    c[qq*4+1] = p0*vv0.y + p1*vv1.y + p2*vv2.y + p3*vv3.y;
                    c[qq*4+2] = p0*vv0.z + p1*vv1.z + p2*vv2.z + p3*vv3.z;
                    c[qq*4+3] = p0*vv0.w + p1*vv1.w + p2*vv2.w + p3*vv3.w;
                }
                // round o=16: keep 4 of 8 (lane bit4 selects logical half)
#pragma unroll
                for (int i = 0; i < 4; ++i) {
                    float send = h16 ? c[i] : c[i + 4];
                    float recv = __shfl_xor_sync(0xffffffffu, send, 16);
                    c[i] = (h16 ? c[i + 4] : c[i]) + recv;
                }
                // round o=8: keep 2 of 4
#pragma unroll
                for (int i = 0; i < 2; ++i) {
                    float send = h8 ? c[i] : c[i + 2];
                    float recv = __shfl_xor_sync(0xffffffffu, send, 8);
                    c[i] = (h8 ? c[i + 2] : c[i]) + recv;
                }
                // round o=4: keep 1 of 2
                {
                    float send = h4 ? c[0] : c[1];
                    float recv = __shfl_xor_sync(0xffffffffu, send, 4);
                    c[0] = (h4 ? c[1] : c[0]) + recv;
                }
                // finish over lane bits {2,1}
                c[0] += __shfl_xor_sync(0xffffffffu, c[0], 2);
                c[0] += __shfl_xor_sync(0xffffffffu, c[0], 1);
                // lane l holds value (l>>2)&7 of this batch, fully reduced
                if ((lane & 3) == 0)
                    ored[w * 33 + batch * 8 + ((lane >> 2) & 7)] = c[0];
            }
        }
    }

    // ---- final head's out reduction
    __syncthreads();
    if (tid < QT * 4) {
        float s = 0.f;
#pragma unroll
        for (int ww = 0; ww < 16; ++ww) s += ored[ww * 33 + tid];
        out[((size_t)(b * NH + NH - 1) * SQ + qb + (tid >> 2)) * 4 + (tid & 3)] = s;
    }
}

extern "C" void kernel_launch(void* const* d_in, const int* in_sizes, int n_in,
                              void* d_out, int out_size)
{
    (void)in_sizes; (void)n_in; (void)out_size;
    const float4* Q    = (const float4*)d_in[0];
    const float4* K    = (const float4*)d_in[1];
    const float4* V    = (const float4*)d_in[2];
    const int*    mask = (const int*)   d_in[3];

    float* outp  = (float*)d_out;
    float* attnp = outp + (size_t)NB * NH * SQ * 4;   // attn follows out

    size_t smem = SMEM_FLOATS * sizeof(float);        // 68352 B -> 2 CTAs/SM
    cudaFuncSetAttribute(mha_kernel, cudaFuncAttributeMaxDynamicSharedMemorySize, (int)smem);

    dim3 grid(SQ / QT, NB);
    mha_kernel<<<grid, THREADS, smem>>>(Q, K, V, mask, outp, (float4*)attnp);
}